// round 16
// baseline (speedup 1.0000x reference)
#include <cuda_runtime.h>
#include <math.h>

#define BATCH 512
#define NLAT  16
#define DIM   128
#define ROWS  (BATCH*NLAT)   /* 8192 */

typedef unsigned long long u64;

/* packed fp32x2 ops (sm_100+): per-lane IEEE FMA at 2x FFMA rate */
#define FMA2(d,a,b,c) asm("fma.rn.f32x2 %0, %1, %2, %3;" : "=l"(d) : "l"(a), "l"(b), "l"(c))
#define MUL2(d,a,b)   asm("mul.rn.f32x2 %0, %1, %2;"     : "=l"(d) : "l"(a), "l"(b))
#define ADD2(d,a,b)   asm("add.rn.f32x2 %0, %1, %2;"     : "=l"(d) : "l"(a), "l"(b))
#define PACK2(d,lo,hi) asm("mov.b64 %0, {%1, %2};" : "=l"(d) : "r"(lo), "r"(hi))
#define UNPK2(lo,hi,x) asm("mov.b64 {%0, %1}, %2;" : "=r"(lo), "=r"(hi) : "l"(x))

/* attention smem layout (floats) */
#define QS_SZ (128*72)
#define KT_SZ (128*132)
#define VS_SZ (128*132)
#define PS_SZ (64*129)
#define ATTN_SMEM_FLOATS (QS_SZ + KT_SZ + VS_SZ + PS_SZ + 64)
#define ATTN_SMEM_BYTES  (ATTN_SMEM_FLOATS*4)

/* ------------------- scratch (no allocations allowed) ------------------- */
__device__ float g_lat [ROWS*DIM];
__device__ float g_nl  [ROWS*DIM];
__device__ float g_qt  [ROWS*512];
__device__ float g_U   [ROWS*512];     /* also reused as head split-K partials */
__device__ float g_f1  [ROWS*256];
__device__ float g_hh  [BATCH*DIM];
__device__ float g_weff [8*DIM*DIM];
__device__ float g_beff [8*DIM];
__device__ float g_qeff [8*DIM*512];
__device__ float g_meff [8*512*DIM];
__device__ float g_qtbia[8*512];
__device__ float g_beff2[8*DIM];
__device__ float g_wcb  [8*512];
__device__ float g_ccb  [32];
__device__ int   g_sd[BATCH], g_ldn[BATCH], g_se[BATCH], g_len[BATCH];

/* ------------------- segment bounds from sorted batch ids --------------- */
__global__ void k_bounds(const int* __restrict__ batch, int n, int maxlen,
                         int* __restrict__ start, int* __restrict__ len)
{
    int b = blockIdx.x * blockDim.x + threadIdx.x;
    if (b >= BATCH) return;
    int lo = 0, hi = n;
    while (lo < hi) { int mid = (lo + hi) >> 1; if (batch[mid] < b) lo = mid + 1; else hi = mid; }
    int s = lo;
    lo = s; hi = n;
    while (lo < hi) { int mid = (lo + hi) >> 1; if (batch[mid] < b + 1) lo = mid + 1; else hi = mid; }
    int L = lo - s;
    if (L > maxlen) L = maxlen;   /* JAX OOB scatter drops tokens beyond maxlen */
    start[b] = s; len[b] = L;
}

__global__ void k_init(const float* __restrict__ latents, float* __restrict__ lat)
{
    int idx = blockIdx.x * blockDim.x + threadIdx.x;
    if (idx < ROWS*DIM) lat[idx] = latents[idx & (NLAT*DIM - 1)];
}

/* ------------------- LayerNorm, one warp per 128-dim row ---------------- */
__global__ void __launch_bounds__(256) k_ln(const float* __restrict__ x,
                                            const float* __restrict__ g,
                                            const float* __restrict__ bt,
                                            float* __restrict__ y, int M)
{
    int row  = blockIdx.x * 8 + (threadIdx.x >> 5);
    int lane = threadIdx.x & 31;
    if (row >= M) return;
    float4 v = *(const float4*)(x + (size_t)row*DIM + lane*4);
    float s = v.x + v.y + v.z + v.w;
#pragma unroll
    for (int o = 16; o > 0; o >>= 1) s += __shfl_xor_sync(0xffffffffu, s, o);
    float m = s * (1.0f/128.0f);
    float d0 = v.x-m, d1 = v.y-m, d2 = v.z-m, d3 = v.w-m;
    float q = d0*d0 + d1*d1 + d2*d2 + d3*d3;
#pragma unroll
    for (int o = 16; o > 0; o >>= 1) q += __shfl_xor_sync(0xffffffffu, q, o);
    float inv = rsqrtf(q * (1.0f/128.0f) + 1e-5f);
    float4 gg = *(const float4*)(g  + lane*4);
    float4 bb = *(const float4*)(bt + lane*4);
    float4 o4;
    o4.x = d0*inv*gg.x + bb.x;  o4.y = d1*inv*gg.y + bb.y;
    o4.z = d2*inv*gg.z + bb.z;  o4.w = d3*inv*gg.w + bb.w;
    *(float4*)(y + (size_t)row*DIM + lane*4) = o4;
}

/* ------------------- generic fp32 GEMM, f32x2 inner --------------------- */
template<int BM, int BN, bool TRANSW, bool BIAS, bool ACCUM, bool RELU>
__global__ void __launch_bounds__(256)
k_gemm(const float* __restrict__ A, int lda, int aSz,
       const float* __restrict__ W, int ldw, int wSz,
       const float* __restrict__ Bv, int bSz,
       float* __restrict__ C, int ldc, int cSz,
       int M, int K)
{
    constexpr int BK = 32;
    constexpr int TX = BN/4;
    constexpr int TY = 256/TX;
    constexpr int RT = BM/TY;
    constexpr int RP = RT/2;
    static_assert(RT >= 2 && (RT & 1) == 0, "RT must be even");
    constexpr int NA = BM*BK/256;
    constexpr int NW = BN*BK/256;
    __shared__ __align__(16) float As[BK][BM+4];
    __shared__ __align__(16) float Ws[BK][BN+4];

    A += (size_t)blockIdx.z * aSz;
    W += (size_t)blockIdx.z * wSz;
    C += (size_t)blockIdx.z * cSz;
    const float* bias = nullptr;
    if (BIAS) bias = Bv + (size_t)blockIdx.z * bSz;

    int t = threadIdx.x;
    int tx = t % TX, ty = t / TX;
    int mBase = blockIdx.x * BM, nBase = blockIdx.y * BN;

    u64 acc[RP][4];
#pragma unroll
    for (int i = 0; i < RP; i++) { acc[i][0]=0ULL; acc[i][1]=0ULL; acc[i][2]=0ULL; acc[i][3]=0ULL; }

    for (int k0 = 0; k0 < K; k0 += BK) {
#pragma unroll
        for (int u = 0; u < NA; u++) {
            int i = t + u*256;
            int r = i >> 5, c = i & 31;
            As[c][r] = A[(size_t)(mBase + r) * lda + k0 + c];
        }
        if (TRANSW) {
#pragma unroll
            for (int u = 0; u < NW; u++) {
                int i = t + u*256;
                int n = i >> 5, c = i & 31;
                Ws[c][n] = W[(size_t)(nBase + n) * ldw + k0 + c];
            }
        } else {
#pragma unroll
            for (int u = 0; u < NW; u++) {
                int i = t + u*256;
                int c = i / BN, n = i % BN;
                Ws[c][n] = W[(size_t)(k0 + c) * ldw + nBase + n];
            }
        }
        __syncthreads();
#pragma unroll
        for (int kk = 0; kk < BK; kk++) {
            float4 b4 = *(const float4*)&Ws[kk][tx*4];
            u64 bp0, bp1, bp2, bp3;
            PACK2(bp0, __float_as_uint(b4.x), __float_as_uint(b4.x));
            PACK2(bp1, __float_as_uint(b4.y), __float_as_uint(b4.y));
            PACK2(bp2, __float_as_uint(b4.z), __float_as_uint(b4.z));
            PACK2(bp3, __float_as_uint(b4.w), __float_as_uint(b4.w));
#pragma unroll
            for (int i = 0; i < RP; i++) {
                u64 ap = *(const u64*)&As[kk][ty*RT + 2*i];
                FMA2(acc[i][0], ap, bp0, acc[i][0]);
                FMA2(acc[i][1], ap, bp1, acc[i][1]);
                FMA2(acc[i][2], ap, bp2, acc[i][2]);
                FMA2(acc[i][3], ap, bp3, acc[i][3]);
            }
        }
        __syncthreads();
    }

#pragma unroll
    for (int i = 0; i < RP; i++) {
        int m0 = mBase + ty*RT + 2*i;
        int n  = nBase + tx*4;
        float r0[4], r1[4];
#pragma unroll
        for (int c = 0; c < 4; c++) {
            unsigned lo, hi;
            UNPK2(lo, hi, acc[i][c]);
            r0[c] = __uint_as_float(lo);
            r1[c] = __uint_as_float(hi);
        }
        if (BIAS) {
            float4 b4 = *(const float4*)(bias + n);
            r0[0]+=b4.x; r0[1]+=b4.y; r0[2]+=b4.z; r0[3]+=b4.w;
            r1[0]+=b4.x; r1[1]+=b4.y; r1[2]+=b4.z; r1[3]+=b4.w;
        }
        if (ACCUM) {
            float4 c0 = *(const float4*)&C[(size_t)m0*ldc + n];
            float4 c1 = *(const float4*)&C[(size_t)(m0+1)*ldc + n];
            r0[0]+=c0.x; r0[1]+=c0.y; r0[2]+=c0.z; r0[3]+=c0.w;
            r1[0]+=c1.x; r1[1]+=c1.y; r1[2]+=c1.z; r1[3]+=c1.w;
        }
        if (RELU) {
#pragma unroll
            for (int c = 0; c < 4; c++) { r0[c]=fmaxf(r0[c],0.f); r1[c]=fmaxf(r1[c],0.f); }
        }
        *(float4*)&C[(size_t)m0*ldc + n]     = make_float4(r0[0],r0[1],r0[2],r0[3]);
        *(float4*)&C[(size_t)(m0+1)*ldc + n] = make_float4(r1[0],r1[1],r1[2],r1[3]);
    }
}

/* ------------------- beff = Wqq @ bq + bq_mha ---------------------------- */
__global__ void k_beff(const float* md_w, const float* me_w,
                       const float* bqd, const float* bqe,
                       const float* mdb, const float* meb, float* beff)
{
    int l = blockIdx.x, s = blockIdx.y, n = threadIdx.x;
    const float* wqq = (s ? me_w : md_w) + l*384*128;
    const float* bq  = (s ? bqe  : bqd ) + l*128;
    const float* bm  = (s ? meb  : mdb ) + l*384;
    float v = bm[n];
    for (int j = 0; j < 128; j++) v += wqq[n*128 + j]*bq[j];
    beff[(l*2 + s)*128 + n] = v;
}

/* ------------------- fold: OUT[a,b] = sum_j X[j*128+a]*Y(j,b) ------------ */
template<bool TR>
__global__ void __launch_bounds__(256) k_fold(
    const float* __restrict__ X, int xl, int xh,
    const float* __restrict__ Y, int yl, int yh,
    float* __restrict__ OUT, int ol, int oh, int ldo)
{
    int l = blockIdx.x >> 2, h = blockIdx.x & 3;
    X   += (size_t)l*xl + (size_t)h*xh;
    Y   += (size_t)l*yl + (size_t)h*yh;
    OUT += (size_t)l*ol + (size_t)h*oh;
    __shared__ float Xs[32][132], Ys[32][132];
    int t = threadIdx.x;
    for (int i = t; i < 32*128; i += 256) {
        int j = i >> 7, a = i & 127;
        Xs[j][a] = X[j*128 + a];
        Ys[j][a] = TR ? Y[a*128 + j] : Y[j*128 + a];
    }
    __syncthreads();
    int a  = t >> 1;
    int b0 = (t & 1) * 64;
    for (int bc = 0; bc < 64; bc += 16) {
        float acc[16];
#pragma unroll
        for (int q = 0; q < 16; q++) acc[q] = 0.f;
        for (int j = 0; j < 32; j++) {
            float xa = Xs[j][a];
#pragma unroll
            for (int q = 0; q < 16; q++) acc[q] += xa * Ys[j][b0+bc+q];
        }
#pragma unroll
        for (int q = 0; q < 16; q++) OUT[a*ldo + b0+bc+q] = acc[q];
    }
}

/* qtbias[pi, h*128+c] = sum_j Wk[h*32+j, c] * beff[pi, h*32+j] */
__global__ void k_qtb(const float* md_w, const float* me_w,
                      const float* beff, float* qtbias)
{
    int l = blockIdx.x, s = blockIdx.y, t = threadIdx.x;  /* 512 threads */
    int pi = l*2 + s;
    const float* mw = (s ? me_w : md_w) + l*384*128 + 128*128;
    int h = t >> 7, c = t & 127;
    const float* be = beff + pi*128 + h*32;
    float v = 0.f;
    for (int j = 0; j < 32; j++) v += mw[(h*32+j)*128 + c] * be[j];
    qtbias[pi*512 + t] = v;
}

/* beff2[pi, n] = ob[n] + sum_m ow[n,m]*bv[m] */
__global__ void k_b2(const float* md_ow, const float* me_ow,
                     const float* md_b, const float* me_b,
                     const float* md_ob, const float* me_ob, float* beff2)
{
    int l = blockIdx.x, s = blockIdx.y, n = threadIdx.x;
    const float* ow = (s ? me_ow : md_ow) + l*16384 + n*128;
    const float* bv = (s ? me_b  : md_b ) + l*384 + 256;
    const float* ob = (s ? me_ob : md_ob) + l*128;
    float v = ob[n];
    for (int m = 0; m < 128; m++) v += ow[m]*bv[m];
    beff2[(l*2+s)*128 + n] = v;
}

/* wcb[pi, h*128+d] = sum_j Weff[pi, h*32+j, d]*bk[h*32+j]; ccb = beff.bk  */
__global__ void k_wcb(const float* md_b, const float* me_b,
                      const float* weff, const float* beff,
                      float* wcb, float* ccb)
{
    int l = blockIdx.x, s = blockIdx.y, t = threadIdx.x;  /* 512 threads */
    int pi = l*2 + s;
    const float* bk = (s ? me_b : md_b) + l*384 + 128;
    int h = t >> 7, d = t & 127;
    const float* wf = weff + pi*16384 + h*32*128;
    float v = 0.f;
    for (int j = 0; j < 32; j++) v += wf[j*128 + d] * bk[h*32 + j];
    wcb[pi*512 + t] = v;
    if (t < 4) {
        float c = 0.f;
        const float* be = beff + pi*128 + t*32;
        for (int j = 0; j < 32; j++) c += be[j] * bk[t*32 + j];
        ccb[pi*4 + t] = c;
    }
}

/* ------------------- flash cross-attention, GEMM-style ------------------- */
/* 256 threads: ty = t>>4 owns 4 (latent,head) pairs; tx = t&15.            */
/* Phase A: S[64,128] = Q@K^T, thread tile 4m x 8j, no reductions.          */
/* Softmax row stats via 16-lane shfl groups.  Phase B: U += P@V, 4m x 8d.  */
__global__ void __launch_bounds__(256, 1)
k_attn(const float* __restrict__ kraw, const float* __restrict__ vraw,
       const int* __restrict__ starts, const int* __restrict__ lens,
       const float* __restrict__ qt, const float* __restrict__ nl,
       const float* __restrict__ wcb, const float* __restrict__ ccb,
       int pi, float* __restrict__ U)
{
    extern __shared__ float smf[];
    float* qs = smf;                    /* [128][72]  Q^T: qs[d][pair]      */
    float* kT = qs + QS_SZ;             /* [128][132] K^T: kT[d][j]         */
    float* vs = kT + KT_SZ;             /* [128][132] V:   vs[j][d]         */
    float* ps = vs + VS_SZ;             /* [64][129]  P:   ps[m][j]         */
    float* cs = ps + PS_SZ;             /* [64] score bias per pair         */

    const float invs = 0.17677669529663687f;  /* 1/sqrt(32) */
    int b = blockIdx.x, t = threadIdx.x;
    int ty = t >> 4, tx = t & 15;
    int row0 = b*NLAT;

    /* load Q transposed: qs[d][li*4+h] = qt[row0+li][h*128+d] */
    for (int i = t; i < NLAT*512; i += 256) {
        int li = i >> 9, col = i & 511;
        int h = col >> 7, d = col & 127;
        qs[d*72 + li*4 + h] = qt[(size_t)(row0+li)*512 + col];
    }
    /* score bias cb[pair] = nl . wcb + ccb (4 lanes per pair) */
    {
        int p = t >> 2, e = t & 3;
        int li = p >> 2, h = p & 3;
        const float* nlr = nl + (size_t)(row0+li)*DIM + e*32;
        const float* w0  = wcb + pi*512 + h*128 + e*32;
        float pa = 0.f;
#pragma unroll
        for (int d = 0; d < 32; d++) pa += nlr[d]*w0[d];
        pa += __shfl_xor_sync(0xffffffffu, pa, 1);
        pa += __shfl_xor_sync(0xffffffffu, pa, 2);
        if (e == 0) cs[p] = pa + ccb[pi*4 + h];
    }
    __syncthreads();
    float cb[4];
#pragma unroll
    for (int mm = 0; mm < 4; mm++) cb[mm] = cs[ty*4 + mm];

    int s0 = starts[b], L = lens[b];
    float mstate[4], lstate[4];
    u64 accU[4][4];
#pragma unroll
    for (int mm = 0; mm < 4; mm++) {
        mstate[mm] = -1e30f; lstate[mm] = 0.f;
        accU[mm][0]=0ULL; accU[mm][1]=0ULL; accU[mm][2]=0ULL; accU[mm][3]=0ULL;
    }

    for (int j0 = 0; j0 < L; j0 += 128) {
        int tc = min(128, L - j0);
        __syncthreads();   /* protect kT/vs/ps from previous tile's phase B */

        /* load K transposed (lanes vary j -> conflict-free STS) and V direct */
        for (int i = t; i < 4096; i += 256) {
            int j = i & 127, c4 = i >> 7;
            if (j < tc) {
                float4 kk = *(const float4*)(kraw + (size_t)(s0+j0+j)*DIM + c4*4);
                kT[(c4*4+0)*132 + j] = kk.x;
                kT[(c4*4+1)*132 + j] = kk.y;
                kT[(c4*4+2)*132 + j] = kk.z;
                kT[(c4*4+3)*132 + j] = kk.w;
            }
        }
        for (int i = t; i < 4096; i += 256) {
            int j = i >> 5, c4 = i & 31;
            if (j < tc)
                *(float4*)(vs + j*132 + c4*4) =
                    *(const float4*)(vraw + (size_t)(s0+j0+j)*DIM + c4*4);
        }
        __syncthreads();

        /* ---- Phase A: scores, 4m x 8j per thread ---- */
        u64 accS[4][4];
#pragma unroll
        for (int mm = 0; mm < 4; mm++) {
            accS[mm][0]=0ULL; accS[mm][1]=0ULL; accS[mm][2]=0ULL; accS[mm][3]=0ULL;
        }
        const float* qp = qs + ty*4;
        const float* kp = kT + tx*8;
#pragma unroll 4
        for (int d = 0; d < 128; d++) {
            float4 qv = *(const float4*)(qp + d*72);
            ulonglong2 k01 = *(const ulonglong2*)(kp + d*132);
            ulonglong2 k23 = *(const ulonglong2*)(kp + d*132 + 4);
            u64 q0, q1, q2, q3;
            PACK2(q0, __float_as_uint(qv.x), __float_as_uint(qv.x));
            PACK2(q1, __float_as_uint(qv.y), __float_as_uint(qv.y));
            PACK2(q2, __float_as_uint(qv.z), __float_as_uint(qv.z));
            PACK2(q3, __float_as_uint(qv.w), __float_as_uint(qv.w));
            FMA2(accS[0][0], q0, k01.x, accS[0][0]);
            FMA2(accS[0][1], q0, k01.y, accS[0][1]);
            FMA2(accS[0][2], q0, k23.x, accS[0][2]);
            FMA2(accS[0][3], q0, k23.y, accS[0][3]);
            FMA2(accS[1][0], q1, k01.x, accS[1][0]);
            FMA2(accS[1][1], q1, k01.y, accS[1][1]);
            FMA2(accS[1][2], q1, k23.x, accS[1][2]);
            FMA2(accS[1][3], q1, k23.y, accS[1][3]);
            FMA2(accS[2][0], q2, k01.x, accS[2][0]);
            FMA2(accS[2][1], q2, k01.y, accS[2][1]);
            FMA2(accS[2][2], q2, k23.x, accS[2][2]);
            FMA2(accS[2][3], q2, k23.y, accS[2][3]);
            FMA2(accS[3][0], q3, k01.x, accS[3][0]);
            FMA2(accS[3][1], q3, k01.y, accS[3][1]);
            FMA2(accS[3][2], q3, k23.x, accS[3][2]);
            FMA2(accS[3][3], q3, k23.y, accS[3][3]);
        }

        /* ---- softmax: row stats via 16-lane shfl, online update ---- */
#pragma unroll
        for (int mm = 0; mm < 4; mm++) {
            float sv[8];
            float rmax = -3e38f;
#pragma unroll
            for (int jp = 0; jp < 4; jp++) {
                unsigned lo, hi;
                UNPK2(lo, hi, accS[mm][jp]);
                float sA = (__uint_as_float(lo) + cb[mm]) * invs;
                float sB = (__uint_as_float(hi) + cb[mm]) * invs;
                if (tx*8 + jp*2     >= tc) sA = -3e38f;
                if (tx*8 + jp*2 + 1 >= tc) sB = -3e38f;
                sv[jp*2] = sA; sv[jp*2+1] = sB;
                rmax = fmaxf(rmax, fmaxf(sA, sB));
            }
#pragma unroll
            for (int o = 1; o < 16; o <<= 1)
                rmax = fmaxf(rmax, __shfl_xor_sync(0xffffffffu, rmax, o));
            float mn = fmaxf(mstate[mm], rmax);
            float sc = __expf(mstate[mm] - mn);
            mstate[mm] = mn;
            float lp = 0.f;
            float* pr = ps + (ty*4+mm)*129 + tx*8;
#pragma unroll
            for (int jj = 0; jj < 8; jj++) {
                float pv = __expf(sv[jj] - mn);
                lp += pv;
                pr[jj] = pv;
            }
#pragma unroll
            for (int o = 1; o < 16; o <<= 1)
                lp += __shfl_xor_sync(0xffffffffu, lp, o);
            lstate[mm] = lstate[mm]*sc + lp;
            u64 sc2; PACK2(sc2, __float_as_uint(sc), __float_as_uint(sc));
#pragma unroll
            for (int dp = 0; dp < 4; dp++) MUL2(accU[mm][dp], accU[mm][dp], sc2);
        }
        __syncthreads();

        /* ---- Phase B: U += P @ V, 4m x 8d per thread ---- */
        const float* vp = vs + tx*8;
        const float* pp0 = ps + (ty*4+0)*129;
        const float* pp1 = ps + (ty*4+1)*129;
        const float* pp2 = ps + (ty*4+2)*129;
        const float* pp3 = ps + (ty*4+3)*129;
#pragma unroll 4
        for (int j = 0; j < tc; j++) {
            float f0 = pp0[j], f1 = pp1[j], f2 = pp2[j], f3 = pp3[j];
            ulonglong2 v01 = *(const ulonglong2*)(vp + j*132);
            ulonglong2 v23 = *(const ulonglong2*)(vp + j*132 + 4);
            u64 w0, w1, w2, w3;
            PACK2(w0, __float_as_uint(f0), __float_as_uint(f0));
            PACK2(w1, __float_as_uint(f1), __float_as_uint(f1));
            PACK2(w2, __float_as_uint(f2), __float_as_uint(f2));
            PACK2(w3, __float_as_uint(f3), __float_as_uint(f3));
            FMA2(accU[0][0], w0, v01.x, accU[0][0]);
            FMA2(accU[0][1], w0, v01.y, accU[0][1]);
            FMA2(accU[0][2], w0, v23.x, accU[0][2]);
            FMA2(accU[0][3], w0, v23.y, accU[0][3]);
            FMA2(accU[1][0], w1, v01.x, accU[1][0]);
            FMA2(accU[1][1], w1, v01.y, accU[1][1]);
            FMA2(accU[1][2], w1, v23.x, accU[1][2]);
            FMA2(accU[1][3], w1, v23.y, accU[1][3]);
            FMA2(accU[2][0], w2, v01.x, accU[2][0]);
            FMA2(accU[2][1], w2, v01.y, accU[2][1]);
            FMA2(accU[2][2], w2, v23.x, accU[2][2]);
            FMA2(accU[2][3], w2, v23.y, accU[2][3]);
            FMA2(accU[3][0], w3, v01.x, accU[3][0]);
            FMA2(accU[3][1], w3, v01.y, accU[3][1]);
            FMA2(accU[3][2], w3, v23.x, accU[3][2]);
            FMA2(accU[3][3], w3, v23.y, accU[3][3]);
        }
    }

    /* normalize + store U[row][h*128 + d] */
#pragma unroll
    for (int mm = 0; mm < 4; mm++) {
        int m = ty*4 + mm;
        float invl = (lstate[mm] > 0.f) ? 1.f/lstate[mm] : 0.f;
        u64 iv; PACK2(iv, __float_as_uint(invl), __float_as_uint(invl));
        ulonglong2 o01, o23;
        MUL2(o01.x, accU[mm][0], iv);
        MUL2(o01.y, accU[mm][1], iv);
        MUL2(o23.x, accU[mm][2], iv);
        MUL2(o23.y, accU[mm][3], iv);
        float* ub = U + (size_t)(row0 + (m>>2))*512 + (m&3)*128 + tx*8;
        *(ulonglong2*)ub       = o01;
        *(ulonglong2*)(ub + 4) = o23;
    }
}

/* ------------------- head split-K reduce: relu(sum_z part + b1) ---------- */
__global__ void k_hred(const float* __restrict__ part, const float* __restrict__ b1,
                       float* __restrict__ hh)
{
    int idx = blockIdx.x * blockDim.x + threadIdx.x;   /* 512*128 */
    float s = b1[idx & 127];
#pragma unroll
    for (int z = 0; z < 16; z++) s += part[z*BATCH*DIM + idx];
    hh[idx] = fmaxf(s, 0.f);
}

/* ------------------- final head: dot + softplus -------------------------- */
__global__ void k_head2(const float* __restrict__ hh, const float* __restrict__ w2,
                        const float* __restrict__ b2, float* __restrict__ out)
{
    int b = blockIdx.x*8 + (threadIdx.x >> 5);
    int lane = threadIdx.x & 31;
    if (b >= BATCH) return;
    float4 h4 = *(const float4*)(hh + (size_t)b*DIM + lane*4);
    float4 w4 = *(const float4*)(w2 + lane*4);
    float s = h4.x*w4.x + h4.y*w4.y + h4.z*w4.z + h4.w*w4.w;
#pragma unroll
    for (int o = 16; o > 0; o >>= 1) s += __shfl_xor_sync(0xffffffffu, s, o);
    s += b2[0];
    float sp = fmaxf(s, 0.f) + log1pf(__expf(-fabsf(s)));
    if (lane == 0) out[b] = sp;
}

/* ------------------------------------------------------------------------ */
extern "C" void kernel_launch(void* const* d_in, const int* in_sizes, int n_in,
                              void* d_out, int out_size)
{
    const float* drug_k = (const float*)d_in[0];
    const float* drug_v = (const float*)d_in[1];
    const float* enz_k  = (const float*)d_in[2];
    const float* enz_v  = (const float*)d_in[3];
    const int*   drug_b = (const int*)d_in[4];
    const int*   enz_b  = (const int*)d_in[5];
    const float* latents= (const float*)d_in[6];
    const float* wq_d   = (const float*)d_in[7];
    const float* bq_d   = (const float*)d_in[8];
    const float* wq_e   = (const float*)d_in[9];
    const float* bq_e   = (const float*)d_in[10];
    const float* md_w   = (const float*)d_in[11];
    const float* md_b   = (const float*)d_in[12];
    const float* md_ow  = (const float*)d_in[13];
    const float* md_ob  = (const float*)d_in[14];
    const float* me_w   = (const float*)d_in[15];
    const float* me_b   = (const float*)d_in[16];
    const float* me_ow  = (const float*)d_in[17];
    const float* me_ob  = (const float*)d_in[18];
    const float* ln1g   = (const float*)d_in[19];
    const float* ln1b   = (const float*)d_in[20];
    const float* ln2g   = (const float*)d_in[21];
    const float* ln2b   = (const float*)d_in[22];
    const float* fw1    = (const float*)d_in[23];
    const float* fb1    = (const float*)d_in[24];
    const float* fw2    = (const float*)d_in[25];
    const float* fb2    = (const float*)d_in[26];
    const float* hw1    = (const float*)d_in[27];
    const float* hb1    = (const float*)d_in[28];
    const float* hw2    = (const float*)d_in[29];
    const float* hb2    = (const float*)d_in[30];

    int nD = in_sizes[0] / DIM;
    int nE = in_sizes[2] / DIM;

    float *lat, *nl, *qtb, *Ub, *f1, *hh, *weff, *beff;
    float *qeff, *meff, *qtbias, *beff2, *wcb, *ccb;
    int *sd, *ldp, *se, *lep;
    cudaGetSymbolAddress((void**)&lat,   g_lat);
    cudaGetSymbolAddress((void**)&nl,    g_nl);
    cudaGetSymbolAddress((void**)&qtb,   g_qt);
    cudaGetSymbolAddress((void**)&Ub,    g_U);
    cudaGetSymbolAddress((void**)&f1,    g_f1);
    cudaGetSymbolAddress((void**)&hh,    g_hh);
    cudaGetSymbolAddress((void**)&weff,  g_weff);
    cudaGetSymbolAddress((void**)&beff,  g_beff);
    cudaGetSymbolAddress((void**)&qeff,  g_qeff);
    cudaGetSymbolAddress((void**)&meff,  g_meff);
    cudaGetSymbolAddress((void**)&qtbias,g_qtbia);
    cudaGetSymbolAddress((void**)&beff2, g_beff2);
    cudaGetSymbolAddress((void**)&wcb,   g_wcb);
    cudaGetSymbolAddress((void**)&ccb,   g_ccb);
    cudaGetSymbolAddress((void**)&sd,    g_sd);
    cudaGetSymbolAddress((void**)&ldp,   g_ldn);
    cudaGetSymbolAddress((void**)&se,    g_se);
    cudaGetSymbolAddress((void**)&lep,   g_len);

    cudaFuncSetAttribute(k_attn, cudaFuncAttributeMaxDynamicSharedMemorySize,
                         ATTN_SMEM_BYTES);

    k_bounds<<<2, 256>>>(drug_b, nD, 128, sd, ldp);
    k_bounds<<<2, 256>>>(enz_b,  nE, 512, se, lep);
    k_init<<<ROWS*DIM/256, 256>>>(latents, lat);

    /* Weff = Wq_mha @ Wq per (layer, side); beff = Wq_mha bq + bq_mha */
    k_gemm<32,128,false,false,false,false><<<dim3(4,1,4), 256>>>(
        md_w, 128, 384*128, wq_d, 128, 128*128, nullptr, 0,
        weff, 128, 2*16384, 128, 128);
    k_gemm<32,128,false,false,false,false><<<dim3(4,1,4), 256>>>(
        me_w, 128, 384*128, wq_e, 128, 128*128, nullptr, 0,
        weff + 16384, 128, 2*16384, 128, 128);
    k_beff<<<dim3(4,2), 128>>>(md_w, me_w, bq_d, bq_e, md_b, me_b, beff);

    /* Qeff[pi][din, h*128+c] = sum_j Weff[h*32+j,din] * Wk[h*32+j,c] */
    k_fold<false><<<16, 256>>>(weff,           32768, 4096,
                               md_w + 128*128, 49152, 4096,
                               qeff,          131072, 128, 512);
    k_fold<false><<<16, 256>>>(weff + 16384,   32768, 4096,
                               me_w + 128*128, 49152, 4096,
                               qeff + 65536,  131072, 128, 512);
    /* Meff[pi][h*128+c, n] = sum_j Wv[h*32+j,c] * ow[n, h*32+j] */
    k_fold<true><<<16, 256>>>(md_w + 256*128, 49152, 4096,
                              md_ow,          16384, 32,
                              meff,          131072, 16384, 128);
    k_fold<true><<<16, 256>>>(me_w + 256*128, 49152, 4096,
                              me_ow,          16384, 32,
                              meff + 65536,  131072, 16384, 128);
    k_qtb<<<dim3(4,2), 512>>>(md_w, me_w, beff, qtbias);
    k_b2 <<<dim3(4,2), 128>>>(md_ow, me_ow, md_b, me_b, md_ob, me_ob, beff2);
    k_wcb<<<dim3(4,2), 512>>>(md_b, me_b, weff, beff, wcb, ccb);

    for (int l = 0; l < 4; l++) {
        k_ln<<<1024, 256>>>(lat, ln1g + l*128, ln1b + l*128, nl, ROWS);
        for (int s = 0; s < 2; s++) {
            const float* kr = s ? enz_k : drug_k;
            const float* vr = s ? enz_v : drug_v;
            const int*   st = s ? se : sd;
            const int*   lp = s ? lep : ldp;
            int pi = l*2 + s;

            /* qt = nl @ Qeff + qtbias   [8192,128]->[8192,512] */
            k_gemm<32,128,false,true,false,false><<<dim3(256,4,1), 256>>>(
                nl, 128, 0, qeff + pi*65536, 512, 0, qtbias + pi*512, 0,
                qtb, 512, 0, ROWS, 128);
            k_attn<<<512, 256, ATTN_SMEM_BYTES>>>(kr, vr, st, lp, qtb, nl,
                                                  wcb, ccb, pi, Ub);
            /* lat += U @ Meff + beff2   [8192,512]->[8192,128] */
            k_gemm<32,128,false,true,true,false><<<dim3(256,1,1), 256>>>(
                Ub, 512, 0, meff + pi*65536, 128, 0, beff2 + pi*128, 0,
                lat, 128, 0, ROWS, 512);
        }
        /* FFN */
        k_ln<<<1024, 256>>>(lat, ln2g + l*128, ln2b + l*128, nl, ROWS);
        k_gemm<32,128,true,true,false,true><<<dim3(256,2,1), 256>>>(
            nl, 128, 0, fw1 + l*256*128, 128, 0, fb1 + l*256, 0,
            f1, 256, 0, ROWS, 128);
        k_gemm<32,128,true,true,true,false><<<dim3(256,1,1), 256>>>(
            f1, 256, 0, fw2 + l*128*256, 256, 0, fb2 + l*128, 0,
            lat, 128, 0, ROWS, 256);
    }

    /* head: split-K over the 16 latents into Ub, then reduce+relu, then dot */
    k_gemm<32,128,true,false,false,false><<<dim3(16,1,16), 256>>>(
        lat, 2048, 128, hw1, 2048, 128, nullptr, 0,
        Ub, 128, BATCH*DIM, BATCH, 128);
    k_hred<<<BATCH*DIM/256, 256>>>(Ub, hb1, hh);
    k_head2<<<64, 256>>>(hh, hw2, hb2, (float*)d_out);
}

// round 17
// speedup vs baseline: 1.9628x; 1.9628x over previous
#include <cuda_runtime.h>
#include <math.h>

#define BATCH 512
#define NLAT  16
#define DIM   128
#define ROWS  (BATCH*NLAT)   /* 8192 */

typedef unsigned long long u64;

/* packed fp32x2 ops (sm_100+): per-lane IEEE FMA at 2x FFMA rate */
#define FMA2(d,a,b,c) asm("fma.rn.f32x2 %0, %1, %2, %3;" : "=l"(d) : "l"(a), "l"(b), "l"(c))
#define MUL2(d,a,b)   asm("mul.rn.f32x2 %0, %1, %2;"     : "=l"(d) : "l"(a), "l"(b))
#define ADD2(d,a,b)   asm("add.rn.f32x2 %0, %1, %2;"     : "=l"(d) : "l"(a), "l"(b))
#define PACK2(d,lo,hi) asm("mov.b64 %0, {%1, %2};" : "=l"(d) : "r"(lo), "r"(hi))
#define UNPK2(lo,hi,x) asm("mov.b64 {%0, %1}, %2;" : "=r"(lo), "=r"(hi) : "l"(x))

/* ------------------- scratch (no allocations allowed) ------------------- */
__device__ float g_lat [ROWS*DIM];
__device__ float g_nl  [ROWS*DIM];
__device__ float g_qt  [ROWS*1024];    /* both sides stacked */
__device__ float g_U   [ROWS*1024];    /* both sides; also head split-K scratch */
__device__ float g_f1  [ROWS*256];
__device__ float g_hh  [BATCH*DIM];
__device__ float g_weff [8*DIM*DIM];
__device__ float g_beff [8*DIM];
__device__ float g_qeff [4*DIM*1024];  /* [l][din][s*512+h*128+c] */
__device__ float g_meff [4*1024*DIM];  /* [l][s*512+h*128+c][n]   */
__device__ float g_qtbia[4*1024];
__device__ float g_b2c  [4*DIM];
__device__ float g_wcb  [4*1024];
__device__ float g_ccb  [32];          /* [l][s][h] */
__device__ int   g_sd[BATCH], g_ldn[BATCH], g_se[BATCH], g_len[BATCH];

/* ------------------- segment bounds from sorted batch ids --------------- */
__global__ void k_bounds(const int* __restrict__ batch, int n, int maxlen,
                         int* __restrict__ start, int* __restrict__ len)
{
    int b = blockIdx.x * blockDim.x + threadIdx.x;
    if (b >= BATCH) return;
    int lo = 0, hi = n;
    while (lo < hi) { int mid = (lo + hi) >> 1; if (batch[mid] < b) lo = mid + 1; else hi = mid; }
    int s = lo;
    lo = s; hi = n;
    while (lo < hi) { int mid = (lo + hi) >> 1; if (batch[mid] < b + 1) lo = mid + 1; else hi = mid; }
    int L = lo - s;
    if (L > maxlen) L = maxlen;   /* JAX OOB scatter drops tokens beyond maxlen */
    start[b] = s; len[b] = L;
}

__global__ void k_init(const float* __restrict__ latents, float* __restrict__ lat)
{
    int idx = blockIdx.x * blockDim.x + threadIdx.x;
    if (idx < ROWS*DIM) lat[idx] = latents[idx & (NLAT*DIM - 1)];
}

/* ------------------- LayerNorm, one warp per 128-dim row ---------------- */
__global__ void __launch_bounds__(256) k_ln(const float* __restrict__ x,
                                            const float* __restrict__ g,
                                            const float* __restrict__ bt,
                                            float* __restrict__ y, int M)
{
    int row  = blockIdx.x * 8 + (threadIdx.x >> 5);
    int lane = threadIdx.x & 31;
    if (row >= M) return;
    float4 v = *(const float4*)(x + (size_t)row*DIM + lane*4);
    float s = v.x + v.y + v.z + v.w;
#pragma unroll
    for (int o = 16; o > 0; o >>= 1) s += __shfl_xor_sync(0xffffffffu, s, o);
    float m = s * (1.0f/128.0f);
    float d0 = v.x-m, d1 = v.y-m, d2 = v.z-m, d3 = v.w-m;
    float q = d0*d0 + d1*d1 + d2*d2 + d3*d3;
#pragma unroll
    for (int o = 16; o > 0; o >>= 1) q += __shfl_xor_sync(0xffffffffu, q, o);
    float inv = rsqrtf(q * (1.0f/128.0f) + 1e-5f);
    float4 gg = *(const float4*)(g  + lane*4);
    float4 bb = *(const float4*)(bt + lane*4);
    float4 o4;
    o4.x = d0*inv*gg.x + bb.x;  o4.y = d1*inv*gg.y + bb.y;
    o4.z = d2*inv*gg.z + bb.z;  o4.w = d3*inv*gg.w + bb.w;
    *(float4*)(y + (size_t)row*DIM + lane*4) = o4;
}

/* ------------------- generic fp32 GEMM, f32x2 inner --------------------- */
template<int BM, int BN, bool TRANSW, bool BIAS, bool ACCUM, bool RELU>
__global__ void __launch_bounds__(256)
k_gemm(const float* __restrict__ A, int lda, int aSz,
       const float* __restrict__ W, int ldw, int wSz,
       const float* __restrict__ Bv, int bSz,
       float* __restrict__ C, int ldc, int cSz,
       int M, int K)
{
    constexpr int BK = 32;
    constexpr int TX = BN/4;
    constexpr int TY = 256/TX;
    constexpr int RT = BM/TY;
    constexpr int RP = RT/2;
    static_assert(RT >= 2 && (RT & 1) == 0, "RT must be even");
    constexpr int NA = BM*BK/256;
    constexpr int NW = BN*BK/256;
    __shared__ __align__(16) float As[BK][BM+4];
    __shared__ __align__(16) float Ws[BK][BN+4];

    A += (size_t)blockIdx.z * aSz;
    W += (size_t)blockIdx.z * wSz;
    C += (size_t)blockIdx.z * cSz;
    const float* bias = nullptr;
    if (BIAS) bias = Bv + (size_t)blockIdx.z * bSz;

    int t = threadIdx.x;
    int tx = t % TX, ty = t / TX;
    int mBase = blockIdx.x * BM, nBase = blockIdx.y * BN;

    u64 acc[RP][4];
#pragma unroll
    for (int i = 0; i < RP; i++) { acc[i][0]=0ULL; acc[i][1]=0ULL; acc[i][2]=0ULL; acc[i][3]=0ULL; }

    for (int k0 = 0; k0 < K; k0 += BK) {
#pragma unroll
        for (int u = 0; u < NA; u++) {
            int i = t + u*256;
            int r = i >> 5, c = i & 31;
            As[c][r] = A[(size_t)(mBase + r) * lda + k0 + c];
        }
        if (TRANSW) {
#pragma unroll
            for (int u = 0; u < NW; u++) {
                int i = t + u*256;
                int n = i >> 5, c = i & 31;
                Ws[c][n] = W[(size_t)(nBase + n) * ldw + k0 + c];
            }
        } else {
#pragma unroll
            for (int u = 0; u < NW; u++) {
                int i = t + u*256;
                int c = i / BN, n = i % BN;
                Ws[c][n] = W[(size_t)(k0 + c) * ldw + nBase + n];
            }
        }
        __syncthreads();
#pragma unroll
        for (int kk = 0; kk < BK; kk++) {
            float4 b4 = *(const float4*)&Ws[kk][tx*4];
            u64 bp0, bp1, bp2, bp3;
            PACK2(bp0, __float_as_uint(b4.x), __float_as_uint(b4.x));
            PACK2(bp1, __float_as_uint(b4.y), __float_as_uint(b4.y));
            PACK2(bp2, __float_as_uint(b4.z), __float_as_uint(b4.z));
            PACK2(bp3, __float_as_uint(b4.w), __float_as_uint(b4.w));
#pragma unroll
            for (int i = 0; i < RP; i++) {
                u64 ap = *(const u64*)&As[kk][ty*RT + 2*i];
                FMA2(acc[i][0], ap, bp0, acc[i][0]);
                FMA2(acc[i][1], ap, bp1, acc[i][1]);
                FMA2(acc[i][2], ap, bp2, acc[i][2]);
                FMA2(acc[i][3], ap, bp3, acc[i][3]);
            }
        }
        __syncthreads();
    }

#pragma unroll
    for (int i = 0; i < RP; i++) {
        int m0 = mBase + ty*RT + 2*i;
        int n  = nBase + tx*4;
        float r0[4], r1[4];
#pragma unroll
        for (int c = 0; c < 4; c++) {
            unsigned lo, hi;
            UNPK2(lo, hi, acc[i][c]);
            r0[c] = __uint_as_float(lo);
            r1[c] = __uint_as_float(hi);
        }
        if (BIAS) {
            float4 b4 = *(const float4*)(bias + n);
            r0[0]+=b4.x; r0[1]+=b4.y; r0[2]+=b4.z; r0[3]+=b4.w;
            r1[0]+=b4.x; r1[1]+=b4.y; r1[2]+=b4.z; r1[3]+=b4.w;
        }
        if (ACCUM) {
            float4 c0 = *(const float4*)&C[(size_t)m0*ldc + n];
            float4 c1 = *(const float4*)&C[(size_t)(m0+1)*ldc + n];
            r0[0]+=c0.x; r0[1]+=c0.y; r0[2]+=c0.z; r0[3]+=c0.w;
            r1[0]+=c1.x; r1[1]+=c1.y; r1[2]+=c1.z; r1[3]+=c1.w;
        }
        if (RELU) {
#pragma unroll
            for (int c = 0; c < 4; c++) { r0[c]=fmaxf(r0[c],0.f); r1[c]=fmaxf(r1[c],0.f); }
        }
        *(float4*)&C[(size_t)m0*ldc + n]     = make_float4(r0[0],r0[1],r0[2],r0[3]);
        *(float4*)&C[(size_t)(m0+1)*ldc + n] = make_float4(r1[0],r1[1],r1[2],r1[3]);
    }
}

/* ------------------- beff = Wqq @ bq + bq_mha ---------------------------- */
__global__ void k_beff(const float* md_w, const float* me_w,
                       const float* bqd, const float* bqe,
                       const float* mdb, const float* meb, float* beff)
{
    int l = blockIdx.x, s = blockIdx.y, n = threadIdx.x;
    const float* wqq = (s ? me_w : md_w) + l*384*128;
    const float* bq  = (s ? bqe  : bqd ) + l*128;
    const float* bm  = (s ? meb  : mdb ) + l*384;
    float v = bm[n];
    for (int j = 0; j < 128; j++) v += wqq[n*128 + j]*bq[j];
    beff[(l*2 + s)*128 + n] = v;
}

/* ------------------- fold: OUT[a,b] = sum_j X[j*128+a]*Y(j,b) ------------ */
template<bool TR>
__global__ void __launch_bounds__(256) k_fold(
    const float* __restrict__ X, int xl, int xh,
    const float* __restrict__ Y, int yl, int yh,
    float* __restrict__ OUT, int ol, int oh, int ldo)
{
    int l = blockIdx.x >> 2, h = blockIdx.x & 3;
    X   += (size_t)l*xl + (size_t)h*xh;
    Y   += (size_t)l*yl + (size_t)h*yh;
    OUT += (size_t)l*ol + (size_t)h*oh;
    __shared__ float Xs[32][132], Ys[32][132];
    int t = threadIdx.x;
    for (int i = t; i < 32*128; i += 256) {
        int j = i >> 7, a = i & 127;
        Xs[j][a] = X[j*128 + a];
        Ys[j][a] = TR ? Y[a*128 + j] : Y[j*128 + a];
    }
    __syncthreads();
    int a  = t >> 1;
    int b0 = (t & 1) * 64;
    for (int bc = 0; bc < 64; bc += 16) {
        float acc[16];
#pragma unroll
        for (int q = 0; q < 16; q++) acc[q] = 0.f;
        for (int j = 0; j < 32; j++) {
            float xa = Xs[j][a];
#pragma unroll
            for (int q = 0; q < 16; q++) acc[q] += xa * Ys[j][b0+bc+q];
        }
#pragma unroll
        for (int q = 0; q < 16; q++) OUT[a*ldo + b0+bc+q] = acc[q];
    }
}

/* qtbias[l, s*512 + h*128+c] = sum_j Wk[h*32+j, c] * beff[pi, h*32+j] */
__global__ void k_qtb(const float* md_w, const float* me_w,
                      const float* beff, float* qtbias)
{
    int l = blockIdx.x, s = blockIdx.y, t = threadIdx.x;  /* 512 threads */
    int pi = l*2 + s;
    const float* mw = (s ? me_w : md_w) + l*384*128 + 128*128;
    int h = t >> 7, c = t & 127;
    const float* be = beff + pi*128 + h*32;
    float v = 0.f;
    for (int j = 0; j < 32; j++) v += mw[(h*32+j)*128 + c] * be[j];
    qtbias[l*1024 + s*512 + t] = v;
}

/* b2c[l, n] = sum_s ( ob_s[n] + sum_m ow_s[n,m]*bv_s[m] ) */
__global__ void k_b2c(const float* md_ow, const float* me_ow,
                      const float* md_b, const float* me_b,
                      const float* md_ob, const float* me_ob, float* b2c)
{
    int l = blockIdx.x, n = threadIdx.x;
    float v = 0.f;
    for (int s = 0; s < 2; s++) {
        const float* ow = (s ? me_ow : md_ow) + l*16384 + n*128;
        const float* bv = (s ? me_b  : md_b ) + l*384 + 256;
        const float* ob = (s ? me_ob : md_ob) + l*128;
        float a = ob[n];
        for (int m = 0; m < 128; m++) a += ow[m]*bv[m];
        v += a;
    }
    b2c[l*128 + n] = v;
}

/* wcb[l, s*512+h*128+d] = sum_j Weff[pi, h*32+j, d]*bk[h*32+j]; ccb=beff.bk */
__global__ void k_wcb(const float* md_b, const float* me_b,
                      const float* weff, const float* beff,
                      float* wcb, float* ccb)
{
    int l = blockIdx.x, s = blockIdx.y, t = threadIdx.x;  /* 512 threads */
    int pi = l*2 + s;
    const float* bk = (s ? me_b : md_b) + l*384 + 128;
    int h = t >> 7, d = t & 127;
    const float* wf = weff + pi*16384 + h*32*128;
    float v = 0.f;
    for (int j = 0; j < 32; j++) v += wf[j*128 + d] * bk[h*32 + j];
    wcb[l*1024 + s*512 + t] = v;
    if (t < 4) {
        float c = 0.f;
        const float* be = beff + pi*128 + t*32;
        for (int j = 0; j < 32; j++) c += be[j] * bk[t*32 + j];
        ccb[l*8 + s*4 + t] = c;
    }
}

/* ------------------- flash cross-attention over raw segments ------------- */
/* 1024 blocks: side = bid&1 (interleaved for packing), b = bid>>1.         */
/* 256 threads = 32 groups x 8 lanes.  Group g owns pairs 2g, 2g+1 (same    */
/* latent, heads h,h+1).  Lane qd owns 16 dims; each k/v LDS feeds 2 pairs. */
__global__ void __launch_bounds__(256, 2)
k_attn(const float* __restrict__ dk, const float* __restrict__ dv,
       const float* __restrict__ ek, const float* __restrict__ ev,
       const int* __restrict__ sd, const int* __restrict__ ld,
       const int* __restrict__ se, const int* __restrict__ le,
       const float* __restrict__ qt, const float* __restrict__ nl,
       const float* __restrict__ wcb, const float* __restrict__ ccb,
       int l, float* __restrict__ U)
{
    __shared__ __align__(16) float ks[32*DIM];
    __shared__ __align__(16) float vs[32*DIM];
    __shared__ float ps[64*33];
    const float invs = 0.17677669529663687f;  /* 1/sqrt(32) */
    int side = blockIdx.x & 1;
    int b    = blockIdx.x >> 1;
    const float* kraw = side ? ek : dk;
    const float* vraw = side ? ev : dv;
    const int* starts = side ? se : sd;
    const int* lens   = side ? le : ld;

    int t = threadIdx.x;
    int g = t >> 3, qd = t & 7;
    int p0 = 2*g, p1 = 2*g + 1;
    int i0 = p0 >> 2, h0 = p0 & 3;            /* h1 = h0+1, same latent */
    int row = b*NLAT + i0;

    /* q regs: 4 chunks of 16B at chunk index c*8+qd */
    const float* qb0 = qt + (size_t)row*1024 + side*512 + h0*128;
    u64 q0[8], q1[8];
#pragma unroll
    for (int c = 0; c < 4; c++) {
        ulonglong2 a = *(const ulonglong2*)(qb0 + (c*8 + qd)*4);
        ulonglong2 d = *(const ulonglong2*)(qb0 + 128 + (c*8 + qd)*4);
        q0[2*c] = a.x; q0[2*c+1] = a.y;
        q1[2*c] = d.x; q1[2*c+1] = d.y;
    }

    /* inline cb = nl . wcb + ccb */
    float cb0, cb1;
    {
        const float* nlr = nl + (size_t)row*DIM;
        const float* w0  = wcb + l*1024 + side*512 + h0*128;
        float pa = 0.f, pb = 0.f;
#pragma unroll
        for (int c = 0; c < 4; c++) {
            int d0 = (c*8 + qd)*4;
#pragma unroll
            for (int e = 0; e < 4; e++) {
                float nv = nlr[d0+e];
                pa += nv * w0[d0+e];
                pb += nv * w0[128 + d0+e];
            }
        }
#pragma unroll
        for (int o = 1; o < 8; o <<= 1) {
            pa += __shfl_xor_sync(0xffffffffu, pa, o);
            pb += __shfl_xor_sync(0xffffffffu, pb, o);
        }
        cb0 = (pa + ccb[l*8 + side*4 + h0]) * invs;
        cb1 = (pb + ccb[l*8 + side*4 + h0 + 1]) * invs;
    }

    int s0 = starts[b], L = lens[b];
    u64 acc0[8], acc1[8];
#pragma unroll
    for (int c = 0; c < 8; c++) { acc0[c] = 0ULL; acc1[c] = 0ULL; }
    float m0 = -1e30f, l0 = 0.f, m1 = -1e30f, l1 = 0.f;

    for (int j0 = 0; j0 < L; j0 += 32) {
        int tc = min(32, L - j0);
        __syncthreads();
#pragma unroll
        for (int u = 0; u < 4; u++) {
            int i = t + u*256;
            int j = i >> 5, c4 = i & 31;
            if (j < tc) {
                const float4* gk = (const float4*)(kraw + (size_t)(s0 + j0 + j)*DIM);
                const float4* gv = (const float4*)(vraw + (size_t)(s0 + j0 + j)*DIM);
                ((float4*)ks)[i] = gk[c4];
                ((float4*)vs)[i] = gv[c4];
            }
        }
        __syncthreads();

        /* scores: S[2 pairs, j] over 128 dims, k LDS shared by both pairs */
        float tm0 = -1e30f, tm1 = -1e30f;
        for (int j = 0; j < tc; j++) {
            const ulonglong2* kr = (const ulonglong2*)(ks + j*DIM);
            u64 pa = 0ULL, pb = 0ULL;
#pragma unroll
            for (int c = 0; c < 4; c++) {
                ulonglong2 kk = kr[c*8 + qd];
                FMA2(pa, q0[2*c],   kk.x, pa);
                FMA2(pa, q0[2*c+1], kk.y, pa);
                FMA2(pb, q1[2*c],   kk.x, pb);
                FMA2(pb, q1[2*c+1], kk.y, pb);
            }
            unsigned lo, hi;
            UNPK2(lo, hi, pa);
            float part0 = __uint_as_float(lo) + __uint_as_float(hi);
            UNPK2(lo, hi, pb);
            float part1 = __uint_as_float(lo) + __uint_as_float(hi);
#pragma unroll
            for (int o = 1; o < 8; o <<= 1) {
                part0 += __shfl_xor_sync(0xffffffffu, part0, o);
                part1 += __shfl_xor_sync(0xffffffffu, part1, o);
            }
            float sj0 = part0*invs + cb0;
            float sj1 = part1*invs + cb1;
            if (qd == 0) { ps[p0*33 + j] = sj0; ps[p1*33 + j] = sj1; }
            tm0 = fmaxf(tm0, sj0);
            tm1 = fmaxf(tm1, sj1);
        }
        __syncwarp();

        /* online softmax rescale */
        float mn0 = fmaxf(m0, tm0), mn1 = fmaxf(m1, tm1);
        float sc0 = __expf(m0 - mn0), sc1 = __expf(m1 - mn1);
        l0 *= sc0; l1 *= sc1;
        u64 s02, s12;
        PACK2(s02, __float_as_uint(sc0), __float_as_uint(sc0));
        PACK2(s12, __float_as_uint(sc1), __float_as_uint(sc1));
#pragma unroll
        for (int c = 0; c < 8; c++) { MUL2(acc0[c], acc0[c], s02); MUL2(acc1[c], acc1[c], s12); }
        m0 = mn0; m1 = mn1;

        /* aggregate: v LDS shared by both pairs */
        for (int j = 0; j < tc; j++) {
            float a0 = __expf(ps[p0*33 + j] - m0);
            float a1 = __expf(ps[p1*33 + j] - m1);
            l0 += a0; l1 += a1;
            u64 a02, a12;
            PACK2(a02, __float_as_uint(a0), __float_as_uint(a0));
            PACK2(a12, __float_as_uint(a1), __float_as_uint(a1));
            const ulonglong2* vr = (const ulonglong2*)(vs + j*DIM);
#pragma unroll
            for (int c = 0; c < 4; c++) {
                ulonglong2 vv = vr[c*8 + qd];
                FMA2(acc0[2*c],   a02, vv.x, acc0[2*c]);
                FMA2(acc0[2*c+1], a02, vv.y, acc0[2*c+1]);
                FMA2(acc1[2*c],   a12, vv.x, acc1[2*c]);
                FMA2(acc1[2*c+1], a12, vv.y, acc1[2*c+1]);
            }
        }
        __syncwarp();
    }

    float inv0 = (l0 > 0.f) ? 1.f/l0 : 0.f;
    float inv1 = (l1 > 0.f) ? 1.f/l1 : 0.f;
    u64 i02, i12;
    PACK2(i02, __float_as_uint(inv0), __float_as_uint(inv0));
    PACK2(i12, __float_as_uint(inv1), __float_as_uint(inv1));
    float* ub = U + (size_t)row*1024 + side*512 + h0*128;
#pragma unroll
    for (int c = 0; c < 4; c++) {
        ulonglong2 o0, o1;
        MUL2(o0.x, acc0[2*c],   i02); MUL2(o0.y, acc0[2*c+1], i02);
        MUL2(o1.x, acc1[2*c],   i12); MUL2(o1.y, acc1[2*c+1], i12);
        *(ulonglong2*)(ub + (c*8 + qd)*4)       = o0;
        *(ulonglong2*)(ub + 128 + (c*8 + qd)*4) = o1;
    }
}

/* ------------------- head split-K reduce: relu(sum_z part + b1) ---------- */
__global__ void k_hred(const float* __restrict__ part, const float* __restrict__ b1,
                       float* __restrict__ hh)
{
    int idx = blockIdx.x * blockDim.x + threadIdx.x;   /* 512*128 */
    float s = b1[idx & 127];
#pragma unroll
    for (int z = 0; z < 16; z++) s += part[z*BATCH*DIM + idx];
    hh[idx] = fmaxf(s, 0.f);
}

/* ------------------- final head: dot + softplus -------------------------- */
__global__ void k_head2(const float* __restrict__ hh, const float* __restrict__ w2,
                        const float* __restrict__ b2, float* __restrict__ out)
{
    int b = blockIdx.x*8 + (threadIdx.x >> 5);
    int lane = threadIdx.x & 31;
    if (b >= BATCH) return;
    float4 h4 = *(const float4*)(hh + (size_t)b*DIM + lane*4);
    float4 w4 = *(const float4*)(w2 + lane*4);
    float s = h4.x*w4.x + h4.y*w4.y + h4.z*w4.z + h4.w*w4.w;
#pragma unroll
    for (int o = 16; o > 0; o >>= 1) s += __shfl_xor_sync(0xffffffffu, s, o);
    s += b2[0];
    float sp = fmaxf(s, 0.f) + log1pf(__expf(-fabsf(s)));
    if (lane == 0) out[b] = sp;
}

/* ------------------------------------------------------------------------ */
extern "C" void kernel_launch(void* const* d_in, const int* in_sizes, int n_in,
                              void* d_out, int out_size)
{
    const float* drug_k = (const float*)d_in[0];
    const float* drug_v = (const float*)d_in[1];
    const float* enz_k  = (const float*)d_in[2];
    const float* enz_v  = (const float*)d_in[3];
    const int*   drug_b = (const int*)d_in[4];
    const int*   enz_b  = (const int*)d_in[5];
    const float* latents= (const float*)d_in[6];
    const float* wq_d   = (const float*)d_in[7];
    const float* bq_d   = (const float*)d_in[8];
    const float* wq_e   = (const float*)d_in[9];
    const float* bq_e   = (const float*)d_in[10];
    const float* md_w   = (const float*)d_in[11];
    const float* md_b   = (const float*)d_in[12];
    const float* md_ow  = (const float*)d_in[13];
    const float* md_ob  = (const float*)d_in[14];
    const float* me_w   = (const float*)d_in[15];
    const float* me_b   = (const float*)d_in[16];
    const float* me_ow  = (const float*)d_in[17];
    const float* me_ob  = (const float*)d_in[18];
    const float* ln1g   = (const float*)d_in[19];
    const float* ln1b   = (const float*)d_in[20];
    const float* ln2g   = (const float*)d_in[21];
    const float* ln2b   = (const float*)d_in[22];
    const float* fw1    = (const float*)d_in[23];
    const float* fb1    = (const float*)d_in[24];
    const float* fw2    = (const float*)d_in[25];
    const float* fb2    = (const float*)d_in[26];
    const float* hw1    = (const float*)d_in[27];
    const float* hb1    = (const float*)d_in[28];
    const float* hw2    = (const float*)d_in[29];
    const float* hb2    = (const float*)d_in[30];

    int nD = in_sizes[0] / DIM;
    int nE = in_sizes[2] / DIM;

    float *lat, *nl, *qtb, *Ub, *f1, *hh, *weff, *beff;
    float *qeff, *meff, *qtbias, *b2c, *wcb, *ccb;
    int *sd, *ldp, *se, *lep;
    cudaGetSymbolAddress((void**)&lat,   g_lat);
    cudaGetSymbolAddress((void**)&nl,    g_nl);
    cudaGetSymbolAddress((void**)&qtb,   g_qt);
    cudaGetSymbolAddress((void**)&Ub,    g_U);
    cudaGetSymbolAddress((void**)&f1,    g_f1);
    cudaGetSymbolAddress((void**)&hh,    g_hh);
    cudaGetSymbolAddress((void**)&weff,  g_weff);
    cudaGetSymbolAddress((void**)&beff,  g_beff);
    cudaGetSymbolAddress((void**)&qeff,  g_qeff);
    cudaGetSymbolAddress((void**)&meff,  g_meff);
    cudaGetSymbolAddress((void**)&qtbias,g_qtbia);
    cudaGetSymbolAddress((void**)&b2c,   g_b2c);
    cudaGetSymbolAddress((void**)&wcb,   g_wcb);
    cudaGetSymbolAddress((void**)&ccb,   g_ccb);
    cudaGetSymbolAddress((void**)&sd,    g_sd);
    cudaGetSymbolAddress((void**)&ldp,   g_ldn);
    cudaGetSymbolAddress((void**)&se,    g_se);
    cudaGetSymbolAddress((void**)&lep,   g_len);

    k_bounds<<<2, 256>>>(drug_b, nD, 128, sd, ldp);
    k_bounds<<<2, 256>>>(enz_b,  nE, 512, se, lep);
    k_init<<<ROWS*DIM/256, 256>>>(latents, lat);

    /* Weff = Wq_mha @ Wq per (layer, side); beff = Wq_mha bq + bq_mha */
    k_gemm<32,128,false,false,false,false><<<dim3(4,1,4), 256>>>(
        md_w, 128, 384*128, wq_d, 128, 128*128, nullptr, 0,
        weff, 128, 2*16384, 128, 128);
    k_gemm<32,128,false,false,false,false><<<dim3(4,1,4), 256>>>(
        me_w, 128, 384*128, wq_e, 128, 128*128, nullptr, 0,
        weff + 16384, 128, 2*16384, 128, 128);
    k_beff<<<dim3(4,2), 128>>>(md_w, me_w, bq_d, bq_e, md_b, me_b, beff);

    /* Qeff[l][din, s*512+h*128+c] = sum_j Weff[pi][h*32+j,din]*Wk[h*32+j,c] */
    k_fold<false><<<16, 256>>>(weff,           32768, 4096,
                               md_w + 128*128, 49152, 4096,
                               qeff,          131072, 128, 1024);
    k_fold<false><<<16, 256>>>(weff + 16384,   32768, 4096,
                               me_w + 128*128, 49152, 4096,
                               qeff + 512,    131072, 128, 1024);
    /* Meff[l][s*512+h*128+c, n] = sum_j Wv[h*32+j,c] * ow[n, h*32+j] */
    k_fold<true><<<16, 256>>>(md_w + 256*128, 49152, 4096,
                              md_ow,          16384, 32,
                              meff,          131072, 16384, 128);
    k_fold<true><<<16, 256>>>(me_w + 256*128, 49152, 4096,
                              me_ow,          16384, 32,
                              meff + 65536,  131072, 16384, 128);
    k_qtb<<<dim3(4,2), 512>>>(md_w, me_w, beff, qtbias);
    k_b2c<<<4, 128>>>(md_ow, me_ow, md_b, me_b, md_ob, me_ob, b2c);
    k_wcb<<<dim3(4,2), 512>>>(md_b, me_b, weff, beff, wcb, ccb);

    for (int l = 0; l < 4; l++) {
        k_ln<<<1024, 256>>>(lat, ln1g + l*128, ln1b + l*128, nl, ROWS);
        /* qt = nl @ Qeff_l + qtbias   [8192,128]->[8192,1024] both sides */
        k_gemm<32,128,false,true,false,false><<<dim3(256,8,1), 256>>>(
            nl, 128, 0, qeff + l*131072, 1024, 0, qtbias + l*1024, 0,
            qtb, 1024, 0, ROWS, 128);
        /* attention, both sides interleaved in one launch */
        k_attn<<<1024, 256>>>(drug_k, drug_v, enz_k, enz_v,
                              sd, ldp, se, lep, qtb, nl, wcb, ccb, l, Ub);
        /* lat += U @ Meff_l + b2c   [8192,1024]->[8192,128], both sides */
        k_gemm<32,128,false,true,true,false><<<dim3(256,1,1), 256>>>(
            Ub, 1024, 0, meff + l*131072, 128, 0, b2c + l*128, 0,
            lat, 128, 0, ROWS, 1024);
        /* FFN */
        k_ln<<<1024, 256>>>(lat, ln2g + l*128, ln2b + l*128, nl, ROWS);
        k_gemm<32,128,true,true,false,true><<<dim3(256,2,1), 256>>>(
            nl, 128, 0, fw1 + l*256*128, 128, 0, fb1 + l*256, 0,
            f1, 256, 0, ROWS, 128);
        k_gemm<32,128,true,true,true,false><<<dim3(256,1,1), 256>>>(
            f1, 256, 0, fw2 + l*128*256, 256, 0, fb2 + l*128, 0,
            lat, 128, 0, ROWS, 256);
    }

    /* head: split-K over the 16 latents into Ub, then reduce+relu, then dot */
    k_gemm<32,128,true,false,false,false><<<dim3(16,1,16), 256>>>(
        lat, 2048, 128, hw1, 2048, 128, nullptr, 0,
        Ub, 128, BATCH*DIM, BATCH, 128);
    k_hred<<<BATCH*DIM/256, 256>>>(Ub, hb1, hh);
    k_head2<<<64, 256>>>(hh, hw2, hb2, (float*)d_out);
}